// round 7
// baseline (speedup 1.0000x reference)
#include <cuda_runtime.h>
#include <cuda_fp16.h>
#include <cstdint>
#include <math.h>

#define N_ROWS 16384
#define DDIM   4096
#define NEXP   256
#define KTOP   6

#define BM 64             // rows per CTA
#define BK 32             // k per stage (two k16 steps)
#define NIT (DDIM / BK)   // 128
#define NTHREADS 512      // 16 warps: 2 (m) x 8 (n), warp tile 32x32
#define LO_SCALE 2048.0f
#define LO_UNSCALE 4.8828125e-4f   // 2^-11

// ---- smem layout (dynamic) ----
// [0,1024): bias; 3 stages at 1024 + s*40960; mst after stages
// stage: A_h 4K | A_l 4K | B_h 16K | B_l 16K = 40K
#define SM_BIAS    0
#define SM_STAGE   1024
#define STAGE_BYTES 40960
#define A_LVL_BYTES 4096
#define B_OFF      8192
#define B_LVL_BYTES 16384
#define SM_MST     (SM_STAGE + 3 * STAGE_BYTES)            // 123904
#define SMEM_TOTAL (SM_MST + 32 * NTHREADS * 4)            // 189440

// scores overlay (after mainloop, over stage region)
#define SSTR 260
#define SM_SCORES  SM_STAGE
#define SM_PB (SM_SCORES + BM * SSTR * 4)
#define SM_PO (SM_PB + BM * 8 * KTOP * 4)
#define SM_PI (SM_PO + BM * 8 * KTOP * 4)

// 4 MB pre-converted, pre-swizzled B: [it(128)][level(2)][n(256)][64B]
__device__ __align__(16) uint8_t g_bpre[(size_t)NIT * 2 * NEXP * 64];

// ---------------------------------------------------------------------------
static __device__ __forceinline__ uint32_t smem_u32(const void* p) {
    uint32_t a;
    asm("{ .reg .u64 t; cvta.to.shared.u64 t, %1; cvt.u32.u64 %0, t; }" : "=r"(a) : "l"(p));
    return a;
}

static __device__ __forceinline__ void sts_u2(uint32_t addr, uint2 v) {
    asm volatile("st.shared.v2.b32 [%0], {%1, %2};"
                 :: "r"(addr), "r"(v.x), "r"(v.y) : "memory");
}

static __device__ __forceinline__ uint32_t pack_h2(__half lo, __half hi) {
    return (uint32_t)__half_as_ushort(lo) | ((uint32_t)__half_as_ushort(hi) << 16);
}

// split fp32x4 into fp16 hi + fp16 lo*2^11 (lo pre-scaled into normal range)
static __device__ __forceinline__ void split2_f4(float4 v, uint2& h, uint2& l) {
    float in[4] = {v.x, v.y, v.z, v.w};
    __half hh[4], hl[4];
#pragma unroll
    for (int i = 0; i < 4; i++) {
        float a = in[i];
        hh[i] = __float2half_rn(a);
        float r = a - __half2float(hh[i]);
        hl[i] = __float2half_rn(r * LO_SCALE);
    }
    h = make_uint2(pack_h2(hh[0], hh[1]), pack_h2(hh[2], hh[3]));
    l = make_uint2(pack_h2(hl[0], hl[1]), pack_h2(hl[2], hl[3]));
}

static __device__ __forceinline__ void ldsm4(uint32_t* r, uint32_t addr) {
    asm volatile("ldmatrix.sync.aligned.m8n8.x4.shared.b16 {%0,%1,%2,%3}, [%4];"
                 : "=r"(r[0]), "=r"(r[1]), "=r"(r[2]), "=r"(r[3]) : "r"(addr));
}

static __device__ __forceinline__ void mma_f16(float* d, const uint32_t* a,
                                               uint32_t b0, uint32_t b1) {
    asm volatile(
        "mma.sync.aligned.m16n8k16.row.col.f32.f16.f16.f32 "
        "{%0,%1,%2,%3}, {%4,%5,%6,%7}, {%8,%9}, {%0,%1,%2,%3};"
        : "+f"(d[0]), "+f"(d[1]), "+f"(d[2]), "+f"(d[3])
        : "r"(a[0]), "r"(a[1]), "r"(a[2]), "r"(a[3]), "r"(b0), "r"(b1));
}

static __device__ __forceinline__ void cpasync16(uint32_t dst, const void* src) {
    asm volatile("cp.async.cg.shared.global [%0], [%1], 16;" :: "r"(dst), "l"(src) : "memory");
}

// 64B-row swizzle: physical 16B chunk = logical chunk ^ ((row>>1)&3)
static __device__ __forceinline__ uint32_t row64_addr(uint32_t base, int row, int lchunk) {
    return base + row * 64 + ((lchunk ^ ((row >> 1) & 3)) << 4);
}

// stable strict-> insertion into top-6 (earlier insert wins ties = lower index)
static __device__ __forceinline__ void ins6(float b, float o, int idx,
                                            float* tb, float* to_, int* ti) {
    if (b > tb[KTOP - 1]) {
        int p = KTOP - 1;
#pragma unroll
        for (int q = KTOP - 1; q > 0; q--) {
            if (b > tb[q - 1]) {
                tb[q] = tb[q - 1]; to_[q] = to_[q - 1]; ti[q] = ti[q - 1];
                p = q - 1;
            }
        }
        tb[p] = b; to_[p] = o; ti[p] = idx;
    }
}

// ---------------------------------------------------------------------------
// Pre-kernel: split B[256][4096] fp32 into fp16 hi + scaled lo, stored as the
// exact per-iteration smem stage image (pre-swizzled 64B rows).
// ---------------------------------------------------------------------------
__global__ __launch_bounds__(256) void preconvert_B(const float* __restrict__ B) {
    int t = blockIdx.x * 256 + threadIdx.x;        // one float4 each; 262144 total
    int n  = t >> 10;                              // row 0..255
    int g  = t & 1023;                             // float4 within row
    int it = g >> 3;                               // k-block (32 floats)
    int kg = g & 7;                                // float4 within block
    float4 v = *reinterpret_cast<const float4*>(&B[(size_t)n * DDIM + g * 4]);
    uint2 h, l;
    split2_f4(v, h, l);
    int pchunk = (kg >> 1) ^ ((n >> 1) & 3);
    size_t off = (size_t)n * 64 + pchunk * 16 + (kg & 1) * 8;
    size_t base = (size_t)it * 2 * B_LVL_BYTES;
    *reinterpret_cast<uint2*>(g_bpre + base + 0 * B_LVL_BYTES + off) = h;
    *reinterpret_cast<uint2*>(g_bpre + base + 1 * B_LVL_BYTES + off) = l;
}

// ---------------------------------------------------------------------------
// Fused main kernel: fp16x2 HMMA GEMM + sqrt-softplus + stable top-6.
// Warp tile 32x32 (2 m-frags x 4 n8-frags): 8 ldsm feed 24 MMAs per k16.
// acc0 = hi*hi (chunk-folded into smem mst every K=256); acc1 = cross terms
// (scaled 2^11, folded once at the end * 2^-11).
// ---------------------------------------------------------------------------
__global__ __launch_bounds__(NTHREADS, 1) void gate_main(
    const float* __restrict__ A, const float* __restrict__ bias,
    float* __restrict__ out) {
    extern __shared__ char smem[];
    const int tid  = threadIdx.x;
    const int lane = tid & 31;
    const int wid  = tid >> 5;
    const int wm   = wid >> 3;          // 0..1
    const int wn   = wid & 7;           // 0..7
    const int mBase = blockIdx.x * BM;
    float* s_bias = reinterpret_cast<float*>(smem + SM_BIAS);
    float* s_mst  = reinterpret_cast<float*>(smem + SM_MST);

    if (tid < NEXP) s_bias[tid] = bias[tid];

    const int g = lane >> 3;            // ldmatrix lane group
    const int l7 = lane & 7;

    float acc0[2][4][4], acc1[2][4][4];
#pragma unroll
    for (int mf = 0; mf < 2; mf++)
#pragma unroll
        for (int j = 0; j < 4; j++)
#pragma unroll
            for (int c = 0; c < 4; c++) { acc0[mf][j][c] = 0.0f; acc1[mf][j][c] = 0.0f; }

    // A LDG task: one float4 per thread
    const int arow = tid >> 3;          // 0..63
    const int akg  = tid & 7;

    const uint32_t sbase = smem_u32(smem) + SM_STAGE;

    // ---- prologue: stages 0 and 1 ----
#pragma unroll
    for (int s = 0; s < 2; s++) {
        uint32_t st = sbase + s * STAGE_BYTES;
#pragma unroll
        for (int j = 0; j < 4; j++) {
            int idx = j * NTHREADS + tid;
            cpasync16(st + B_OFF + idx * 16,
                      g_bpre + (size_t)s * 2 * B_LVL_BYTES + idx * 16);
        }
        asm volatile("cp.async.commit_group;" ::: "memory");
        float4 v = *reinterpret_cast<const float4*>(
            &A[(size_t)(mBase + arow) * DDIM + s * BK + akg * 4]);
        uint2 h, l;
        split2_f4(v, h, l);
        int lchunk = akg >> 1, half = (akg & 1) * 8;
        sts_u2(row64_addr(st + 0 * A_LVL_BYTES, arow, lchunk) + half, h);
        sts_u2(row64_addr(st + 1 * A_LVL_BYTES, arow, lchunk) + half, l);
    }
    asm volatile("cp.async.wait_group 1;" ::: "memory");
    __syncthreads();

#pragma unroll 1
    for (int it = 0; it < NIT; it++) {
        const uint32_t stage = sbase + (it % 3) * STAGE_BYTES;

        float4 areg;
        if (it + 2 < NIT) {
            const uint32_t nstage = sbase + ((it + 2) % 3) * STAGE_BYTES;
#pragma unroll
            for (int j = 0; j < 4; j++) {
                int idx = j * NTHREADS + tid;
                cpasync16(nstage + B_OFF + idx * 16,
                          g_bpre + (size_t)(it + 2) * 2 * B_LVL_BYTES + idx * 16);
            }
            asm volatile("cp.async.commit_group;" ::: "memory");
            areg = *reinterpret_cast<const float4*>(
                &A[(size_t)(mBase + arow) * DDIM + (it + 2) * BK + akg * 4]);
        }

        // ---- compute current stage: 2 k16 steps ----
#pragma unroll
        for (int ks = 0; ks < 2; ks++) {
            uint32_t ah[2][4], al[2][4];
#pragma unroll
            for (int mf = 0; mf < 2; mf++) {
                int row = wm * 32 + mf * 16 + (g & 1) * 8 + l7;
                int lchunk = ks * 2 + (g >> 1);
                ldsm4(ah[mf], row64_addr(stage + 0 * A_LVL_BYTES, row, lchunk));
                ldsm4(al[mf], row64_addr(stage + 1 * A_LVL_BYTES, row, lchunk));
            }
            int lchb = ks * 2 + (g & 1);
#pragma unroll
            for (int nf2 = 0; nf2 < 2; nf2++) {
                int rowb = wn * 32 + nf2 * 16 + (g >> 1) * 8 + l7;
                uint32_t bh[4], bl[4];
                ldsm4(bh, row64_addr(stage + B_OFF + 0 * B_LVL_BYTES, rowb, lchb));
                ldsm4(bl, row64_addr(stage + B_OFF + 1 * B_LVL_BYTES, rowb, lchb));
#pragma unroll
                for (int mf = 0; mf < 2; mf++) {
                    mma_f16(acc0[mf][nf2 * 2 + 0], ah[mf], bh[0], bh[1]);
                    mma_f16(acc0[mf][nf2 * 2 + 1], ah[mf], bh[2], bh[3]);
                    mma_f16(acc1[mf][nf2 * 2 + 0], ah[mf], bl[0], bl[1]);
                    mma_f16(acc1[mf][nf2 * 2 + 1], ah[mf], bl[2], bl[3]);
                    mma_f16(acc1[mf][nf2 * 2 + 0], al[mf], bh[0], bh[1]);
                    mma_f16(acc1[mf][nf2 * 2 + 1], al[mf], bh[2], bh[3]);
                }
            }
        }

        if (it + 2 < NIT) {
            const uint32_t nstage = sbase + ((it + 2) % 3) * STAGE_BYTES;
            uint2 h, l;
            split2_f4(areg, h, l);
            int lchunk = akg >> 1, half = (akg & 1) * 8;
            sts_u2(row64_addr(nstage + 0 * A_LVL_BYTES, arow, lchunk) + half, h);
            sts_u2(row64_addr(nstage + 1 * A_LVL_BYTES, arow, lchunk) + half, l);
        }

        // fold hi*hi chunk into smem master every 8 iterations (K chunk = 256)
        if ((it & 7) == 7) {
            if (it == 7) {
#pragma unroll
                for (int mf = 0; mf < 2; mf++)
#pragma unroll
                    for (int j = 0; j < 4; j++)
#pragma unroll
                        for (int c = 0; c < 4; c++) {
                            s_mst[((mf * 4 + j) * 4 + c) * NTHREADS + tid] = acc0[mf][j][c];
                            acc0[mf][j][c] = 0.0f;
                        }
            } else {
#pragma unroll
                for (int mf = 0; mf < 2; mf++)
#pragma unroll
                    for (int j = 0; j < 4; j++)
#pragma unroll
                        for (int c = 0; c < 4; c++) {
                            s_mst[((mf * 4 + j) * 4 + c) * NTHREADS + tid] += acc0[mf][j][c];
                            acc0[mf][j][c] = 0.0f;
                        }
            }
        }

        if (it + 2 < NIT) {
            asm volatile("cp.async.wait_group 1;" ::: "memory");
        } else if (it + 1 < NIT) {
            asm volatile("cp.async.wait_group 0;" ::: "memory");
        }
        __syncthreads();
    }

    // ---- write scores to smem (overlay stages): score = mst + acc1 * 2^-11 ----
    float* sc = reinterpret_cast<float*>(smem + SM_SCORES);
#pragma unroll
    for (int mf = 0; mf < 2; mf++) {
#pragma unroll
        for (int nf = 0; nf < 4; nf++) {
            int m0 = wm * 32 + mf * 16 + (lane >> 2);
            int n0 = wn * 32 + nf * 8 + (lane & 3) * 2;
            int jb = (mf * 4 + nf) * 4;
            float s0 = s_mst[(jb + 0) * NTHREADS + tid] + acc1[mf][nf][0] * LO_UNSCALE;
            float s1 = s_mst[(jb + 1) * NTHREADS + tid] + acc1[mf][nf][1] * LO_UNSCALE;
            float s2 = s_mst[(jb + 2) * NTHREADS + tid] + acc1[mf][nf][2] * LO_UNSCALE;
            float s3 = s_mst[(jb + 3) * NTHREADS + tid] + acc1[mf][nf][3] * LO_UNSCALE;
            *reinterpret_cast<float2*>(&sc[m0 * SSTR + n0]) = make_float2(s0, s1);
            *reinterpret_cast<float2*>(&sc[(m0 + 8) * SSTR + n0]) = make_float2(s2, s3);
        }
    }
    __syncthreads();

    // ---- top-6: 8 threads per row, each scans 32 experts, then merge ----
    {
        const int r = tid >> 3;     // row 0..63
        const int q = tid & 7;      // eighth
        float tb[KTOP], to_[KTOP];
        int ti[KTOP];
#pragma unroll
        for (int i = 0; i < KTOP; i++) { tb[i] = -1e30f; to_[i] = 0.0f; ti[i] = 0; }
#pragma unroll 4
        for (int j = 0; j < 32; j++) {
            int e = q * 32 + j;
            float z = sc[r * SSTR + e];
            float sp = fmaxf(z, 0.0f) + log1pf(expf(-fabsf(z)));
            float o = sqrtf(sp);
            ins6(o + s_bias[e], o, e, tb, to_, ti);
        }
        float* pb = reinterpret_cast<float*>(smem + SM_PB);
        float* po = reinterpret_cast<float*>(smem + SM_PO);
        int*   pi = reinterpret_cast<int*>(smem + SM_PI);
#pragma unroll
        for (int i = 0; i < KTOP; i++) {
            pb[(r * 8 + q) * KTOP + i] = tb[i];
            po[(r * 8 + q) * KTOP + i] = to_[i];
            pi[(r * 8 + q) * KTOP + i] = ti[i];
        }
        __syncthreads();

        if (q == 0) {
            float fb[KTOP], fo[KTOP];
            int fi[KTOP];
#pragma unroll
            for (int i = 0; i < KTOP; i++) { fb[i] = -1e30f; fo[i] = 0.0f; fi[i] = 0; }
#pragma unroll
            for (int q2 = 0; q2 < 8; q2++)
#pragma unroll
                for (int i = 0; i < KTOP; i++)
                    ins6(pb[(r * 8 + q2) * KTOP + i], po[(r * 8 + q2) * KTOP + i],
                         pi[(r * 8 + q2) * KTOP + i], fb, fo, fi);
            float sum = 0.0f;
#pragma unroll
            for (int i = 0; i < KTOP; i++) sum += fo[i];
            const float s = 1.5f / sum;
            const size_t row = (size_t)(mBase + r);
#pragma unroll
            for (int i = 0; i < KTOP; i++) {
                out[row * KTOP + i] = fo[i] * s;
                out[(size_t)N_ROWS * KTOP + row * KTOP + i] = (float)fi[i];
            }
        }
    }
}

extern "C" void kernel_launch(void* const* d_in, const int* in_sizes, int n_in,
                              void* d_out, int out_size) {
    const float* x      = (const float*)d_in[0];   // [N, D]
    const float* weight = (const float*)d_in[1];   // [E, D]
    const float* bias   = (const float*)d_in[2];   // [E]
    float* out = (float*)d_out;

    preconvert_B<<<(NEXP * DDIM / 4) / 256, 256>>>(weight);
    cudaFuncSetAttribute(gate_main, cudaFuncAttributeMaxDynamicSharedMemorySize, SMEM_TOTAL);
    gate_main<<<N_ROWS / BM, NTHREADS, SMEM_TOTAL>>>(x, bias, out);
}

// round 8
// speedup vs baseline: 1.0061x; 1.0061x over previous
#include <cuda_runtime.h>
#include <cuda_fp16.h>
#include <cstdint>
#include <math.h>

#define N_ROWS 16384
#define DDIM   4096
#define NEXP   256
#define KTOP   6

#define BM 64             // rows per CTA
#define BK 64             // k per stage (four k16 steps)
#define NIT (DDIM / BK)   // 64
#define NTHREADS 512      // 16 warps: 2 (m) x 8 (n), warp tile 32x32
#define LO_SCALE 2048.0f
#define LO_UNSCALE 4.8828125e-4f   // 2^-11

// ---- smem layout (dynamic) ----
// [0,1024): bias; 2 stages at 1024 + s*81920; mst after stages
// stage: A = [sub0 hi 4K][sub0 lo 4K][sub1 hi 4K][sub1 lo 4K] (16K)
//        B = [sub0 hi 16K][sub0 lo 16K][sub1 hi 16K][sub1 lo 16K] (64K)
#define SM_BIAS    0
#define SM_STAGE   1024
#define STAGE_BYTES 81920
#define A_LVL 4096
#define A_SUB 8192
#define B_OFF 16384
#define B_LVL 16384
#define B_SUB 32768
#define SM_MST     (SM_STAGE + 2 * STAGE_BYTES)            // 164864
#define SMEM_TOTAL (SM_MST + 32 * NTHREADS * 4)            // 230400

// scores overlay (after mainloop, over stage region)
#define SSTR 260
#define SM_SCORES  SM_STAGE
#define SM_PB (SM_SCORES + BM * SSTR * 4)
#define SM_PO (SM_PB + BM * 8 * KTOP * 4)
#define SM_PI (SM_PO + BM * 8 * KTOP * 4)

// 4 MB pre-converted, pre-swizzled B: [k32-block(128)][level(2)][n(256)][64B]
// Two consecutive k32-blocks are contiguous = one BK=64 stage image.
__device__ __align__(16) uint8_t g_bpre[(size_t)128 * 2 * NEXP * 64];

// ---------------------------------------------------------------------------
static __device__ __forceinline__ uint32_t smem_u32(const void* p) {
    uint32_t a;
    asm("{ .reg .u64 t; cvta.to.shared.u64 t, %1; cvt.u32.u64 %0, t; }" : "=r"(a) : "l"(p));
    return a;
}

static __device__ __forceinline__ void sts_u2(uint32_t addr, uint2 v) {
    asm volatile("st.shared.v2.b32 [%0], {%1, %2};"
                 :: "r"(addr), "r"(v.x), "r"(v.y) : "memory");
}

static __device__ __forceinline__ uint32_t pack_h2(__half lo, __half hi) {
    return (uint32_t)__half_as_ushort(lo) | ((uint32_t)__half_as_ushort(hi) << 16);
}

// split fp32x4 into fp16 hi + fp16 lo*2^11 (lo pre-scaled into normal range)
static __device__ __forceinline__ void split2_f4(float4 v, uint2& h, uint2& l) {
    float in[4] = {v.x, v.y, v.z, v.w};
    __half hh[4], hl[4];
#pragma unroll
    for (int i = 0; i < 4; i++) {
        float a = in[i];
        hh[i] = __float2half_rn(a);
        float r = a - __half2float(hh[i]);
        hl[i] = __float2half_rn(r * LO_SCALE);
    }
    h = make_uint2(pack_h2(hh[0], hh[1]), pack_h2(hh[2], hh[3]));
    l = make_uint2(pack_h2(hl[0], hl[1]), pack_h2(hl[2], hl[3]));
}

static __device__ __forceinline__ void ldsm4(uint32_t* r, uint32_t addr) {
    asm volatile("ldmatrix.sync.aligned.m8n8.x4.shared.b16 {%0,%1,%2,%3}, [%4];"
                 : "=r"(r[0]), "=r"(r[1]), "=r"(r[2]), "=r"(r[3]) : "r"(addr));
}

// NOTE: non-volatile — pure register computation, lets the compiler interleave
static __device__ __forceinline__ void mma_f16(float* d, const uint32_t* a,
                                               uint32_t b0, uint32_t b1) {
    asm("mma.sync.aligned.m16n8k16.row.col.f32.f16.f16.f32 "
        "{%0,%1,%2,%3}, {%4,%5,%6,%7}, {%8,%9}, {%0,%1,%2,%3};"
        : "+f"(d[0]), "+f"(d[1]), "+f"(d[2]), "+f"(d[3])
        : "r"(a[0]), "r"(a[1]), "r"(a[2]), "r"(a[3]), "r"(b0), "r"(b1));
}

static __device__ __forceinline__ void cpasync16(uint32_t dst, const void* src) {
    asm volatile("cp.async.cg.shared.global [%0], [%1], 16;" :: "r"(dst), "l"(src) : "memory");
}

// 64B-row swizzle: physical 16B chunk = logical chunk ^ ((row>>1)&3)
static __device__ __forceinline__ uint32_t row64_addr(uint32_t base, int row, int lchunk) {
    return base + row * 64 + ((lchunk ^ ((row >> 1) & 3)) << 4);
}

// stable strict-> insertion into top-6 (earlier insert wins ties = lower index)
static __device__ __forceinline__ void ins6(float b, float o, int idx,
                                            float* tb, float* to_, int* ti) {
    if (b > tb[KTOP - 1]) {
        int p = KTOP - 1;
#pragma unroll
        for (int q = KTOP - 1; q > 0; q--) {
            if (b > tb[q - 1]) {
                tb[q] = tb[q - 1]; to_[q] = to_[q - 1]; ti[q] = ti[q - 1];
                p = q - 1;
            }
        }
        tb[p] = b; to_[p] = o; ti[p] = idx;
    }
}

// ---------------------------------------------------------------------------
// Pre-kernel: split B[256][4096] fp32 into fp16 hi + scaled lo, stored as the
// exact per-k32-block smem image (pre-swizzled 64B rows).
// ---------------------------------------------------------------------------
__global__ __launch_bounds__(256) void preconvert_B(const float* __restrict__ B) {
    int t = blockIdx.x * 256 + threadIdx.x;        // one float4 each; 262144 total
    int n  = t >> 10;                              // row 0..255
    int g  = t & 1023;                             // float4 within row
    int it = g >> 3;                               // k32-block
    int kg = g & 7;                                // float4 within block
    float4 v = *reinterpret_cast<const float4*>(&B[(size_t)n * DDIM + g * 4]);
    uint2 h, l;
    split2_f4(v, h, l);
    int pchunk = (kg >> 1) ^ ((n >> 1) & 3);
    size_t off = (size_t)n * 64 + pchunk * 16 + (kg & 1) * 8;
    size_t base = (size_t)it * 2 * B_LVL;
    *reinterpret_cast<uint2*>(g_bpre + base + 0 * B_LVL + off) = h;
    *reinterpret_cast<uint2*>(g_bpre + base + 1 * B_LVL + off) = l;
}

// ---------------------------------------------------------------------------
// Fused main kernel: fp16x2 HMMA GEMM + sqrt-softplus + stable top-6.
// BK=64 stages (2-deep ping-pong): half the barriers of the BK=32 version.
// acc0 = hi*hi (chunk-folded into smem mst every K=256); acc1 = cross terms
// (scaled 2^11, folded once at the end * 2^-11).
// ---------------------------------------------------------------------------
__global__ __launch_bounds__(NTHREADS, 1) void gate_main(
    const float* __restrict__ A, const float* __restrict__ bias,
    float* __restrict__ out) {
    extern __shared__ char smem[];
    const int tid  = threadIdx.x;
    const int lane = tid & 31;
    const int wid  = tid >> 5;
    const int wm   = wid >> 3;          // 0..1
    const int wn   = wid & 7;           // 0..7
    const int mBase = blockIdx.x * BM;
    float* s_bias = reinterpret_cast<float*>(smem + SM_BIAS);
    float* s_mst  = reinterpret_cast<float*>(smem + SM_MST);

    if (tid < NEXP) s_bias[tid] = bias[tid];

    const int g = lane >> 3;            // ldmatrix lane group
    const int l7 = lane & 7;

    float acc0[2][4][4], acc1[2][4][4];
#pragma unroll
    for (int mf = 0; mf < 2; mf++)
#pragma unroll
        for (int j = 0; j < 4; j++)
#pragma unroll
            for (int c = 0; c < 4; c++) { acc0[mf][j][c] = 0.0f; acc1[mf][j][c] = 0.0f; }

    // A tasks: 2 float4 per thread per stage (row arow, cols akg0*4 and (akg0+8)*4)
    const int arow = tid >> 3;          // 0..63
    const int akg0 = tid & 7;

    const uint32_t sbase = smem_u32(smem) + SM_STAGE;

    // ---- prologue: stage 0 ----
    {
        uint32_t st = sbase;
#pragma unroll
        for (int j = 0; j < 8; j++) {
            int idx = j * NTHREADS + tid;
            cpasync16(st + B_OFF + idx * 16, g_bpre + idx * 16);
        }
        asm volatile("cp.async.commit_group;" ::: "memory");
#pragma unroll
        for (int s = 0; s < 2; s++) {
            int akg = akg0 + s * 8;     // 0..15; sub = s
            float4 v = *reinterpret_cast<const float4*>(
                &A[(size_t)(mBase + arow) * DDIM + akg * 4]);
            uint2 h, l;
            split2_f4(v, h, l);
            int kg = akg & 7;
            int lchunk = kg >> 1, half = (kg & 1) * 8;
            uint32_t ab = st + s * A_SUB;
            sts_u2(row64_addr(ab, arow, lchunk) + half, h);
            sts_u2(row64_addr(ab + A_LVL, arow, lchunk) + half, l);
        }
        asm volatile("cp.async.wait_group 0;" ::: "memory");
        __syncthreads();
    }

#pragma unroll 1
    for (int it = 0; it < NIT; it++) {
        const uint32_t stage  = sbase + (it & 1) * STAGE_BYTES;
        const uint32_t nstage = sbase + ((it + 1) & 1) * STAGE_BYTES;

        float4 areg[2];
        if (it + 1 < NIT) {
#pragma unroll
            for (int j = 0; j < 8; j++) {
                int idx = j * NTHREADS + tid;
                cpasync16(nstage + B_OFF + idx * 16,
                          g_bpre + (size_t)(it + 1) * 2 * B_SUB + idx * 16);
            }
            asm volatile("cp.async.commit_group;" ::: "memory");
#pragma unroll
            for (int s = 0; s < 2; s++)
                areg[s] = *reinterpret_cast<const float4*>(
                    &A[(size_t)(mBase + arow) * DDIM + (it + 1) * BK + (akg0 + s * 8) * 4]);
        }

        // ---- compute current stage: 4 k16 steps ----
#pragma unroll
        for (int ks = 0; ks < 4; ks++) {
            const int sub = ks >> 1, ksl = ks & 1;
            uint32_t ah[2][4], al[2][4];
#pragma unroll
            for (int mf = 0; mf < 2; mf++) {
                int row = wm * 32 + mf * 16 + (g & 1) * 8 + l7;
                int lchunk = ksl * 2 + (g >> 1);
                uint32_t ab = stage + sub * A_SUB;
                ldsm4(ah[mf], row64_addr(ab, row, lchunk));
                ldsm4(al[mf], row64_addr(ab + A_LVL, row, lchunk));
            }
            int lchb = ksl * 2 + (g & 1);
            const uint32_t bb = stage + B_OFF + sub * B_SUB;
#pragma unroll
            for (int nf2 = 0; nf2 < 2; nf2++) {
                int rowb = wn * 32 + nf2 * 16 + (g >> 1) * 8 + l7;
                uint32_t bh[4], bl[4];
                ldsm4(bh, row64_addr(bb, rowb, lchb));
                ldsm4(bl, row64_addr(bb + B_LVL, rowb, lchb));
#pragma unroll
                for (int mf = 0; mf < 2; mf++) {
                    mma_f16(acc0[mf][nf2 * 2 + 0], ah[mf], bh[0], bh[1]);
                    mma_f16(acc0[mf][nf2 * 2 + 1], ah[mf], bh[2], bh[3]);
                    mma_f16(acc1[mf][nf2 * 2 + 0], ah[mf], bl[0], bl[1]);
                    mma_f16(acc1[mf][nf2 * 2 + 1], ah[mf], bl[2], bl[3]);
                    mma_f16(acc1[mf][nf2 * 2 + 0], al[mf], bh[0], bh[1]);
                    mma_f16(acc1[mf][nf2 * 2 + 1], al[mf], bh[2], bh[3]);
                }
            }
        }

        if (it + 1 < NIT) {
#pragma unroll
            for (int s = 0; s < 2; s++) {
                uint2 h, l;
                split2_f4(areg[s], h, l);
                int kg = akg0;          // kg within sub-block (0..7)
                int lchunk = kg >> 1, half = (kg & 1) * 8;
                uint32_t ab = nstage + s * A_SUB;
                sts_u2(row64_addr(ab, arow, lchunk) + half, h);
                sts_u2(row64_addr(ab + A_LVL, arow, lchunk) + half, l);
            }
        }

        // fold hi*hi chunk into smem master every 4 iterations (K chunk = 256)
        if ((it & 3) == 3) {
            if (it == 3) {
#pragma unroll
                for (int mf = 0; mf < 2; mf++)
#pragma unroll
                    for (int j = 0; j < 4; j++)
#pragma unroll
                        for (int c = 0; c < 4; c++) {
                            s_mst[((mf * 4 + j) * 4 + c) * NTHREADS + tid] = acc0[mf][j][c];
                            acc0[mf][j][c] = 0.0f;
                        }
            } else {
#pragma unroll
                for (int mf = 0; mf < 2; mf++)
#pragma unroll
                    for (int j = 0; j < 4; j++)
#pragma unroll
                        for (int c = 0; c < 4; c++) {
                            s_mst[((mf * 4 + j) * 4 + c) * NTHREADS + tid] += acc0[mf][j][c];
                            acc0[mf][j][c] = 0.0f;
                        }
            }
        }

        if (it + 1 < NIT)
            asm volatile("cp.async.wait_group 0;" ::: "memory");
        __syncthreads();
    }

    // ---- write scores to smem (overlay stages): score = mst + acc1 * 2^-11 ----
    float* sc = reinterpret_cast<float*>(smem + SM_SCORES);
#pragma unroll
    for (int mf = 0; mf < 2; mf++) {
#pragma unroll
        for (int nf = 0; nf < 4; nf++) {
            int m0 = wm * 32 + mf * 16 + (lane >> 2);
            int n0 = wn * 32 + nf * 8 + (lane & 3) * 2;
            int jb = (mf * 4 + nf) * 4;
            float s0 = s_mst[(jb + 0) * NTHREADS + tid] + acc1[mf][nf][0] * LO_UNSCALE;
            float s1 = s_mst[(jb + 1) * NTHREADS + tid] + acc1[mf][nf][1] * LO_UNSCALE;
            float s2 = s_mst[(jb + 2) * NTHREADS + tid] + acc1[mf][nf][2] * LO_UNSCALE;
            float s3 = s_mst[(jb + 3) * NTHREADS + tid] + acc1[mf][nf][3] * LO_UNSCALE;
            *reinterpret_cast<float2*>(&sc[m0 * SSTR + n0]) = make_float2(s0, s1);
            *reinterpret_cast<float2*>(&sc[(m0 + 8) * SSTR + n0]) = make_float2(s2, s3);
        }
    }
    __syncthreads();

    // ---- top-6: 8 threads per row, each scans 32 experts, then merge ----
    {
        const int r = tid >> 3;     // row 0..63
        const int q = tid & 7;      // eighth
        float tb[KTOP], to_[KTOP];
        int ti[KTOP];
#pragma unroll
        for (int i = 0; i < KTOP; i++) { tb[i] = -1e30f; to_[i] = 0.0f; ti[i] = 0; }
#pragma unroll 4
        for (int j = 0; j < 32; j++) {
            int e = q * 32 + j;
            float z = sc[r * SSTR + e];
            float sp = fmaxf(z, 0.0f) + log1pf(expf(-fabsf(z)));
            float o = sqrtf(sp);
            ins6(o + s_bias[e], o, e, tb, to_, ti);
        }
        float* pb = reinterpret_cast<float*>(smem + SM_PB);
        float* po = reinterpret_cast<float*>(smem + SM_PO);
        int*   pi = reinterpret_cast<int*>(smem + SM_PI);
#pragma unroll
        for (int i = 0; i < KTOP; i++) {
            pb[(r * 8 + q) * KTOP + i] = tb[i];
            po[(r * 8 + q) * KTOP + i] = to_[i];
            pi[(r * 8 + q) * KTOP + i] = ti[i];
        }
        __syncthreads();

        if (q == 0) {
            float fb[KTOP], fo[KTOP];
            int fi[KTOP];
#pragma unroll
            for (int i = 0; i < KTOP; i++) { fb[i] = -1e30f; fo[i] = 0.0f; fi[i] = 0; }
#pragma unroll
            for (int q2 = 0; q2 < 8; q2++)
#pragma unroll
                for (int i = 0; i < KTOP; i++)
                    ins6(pb[(r * 8 + q2) * KTOP + i], po[(r * 8 + q2) * KTOP + i],
                         pi[(r * 8 + q2) * KTOP + i], fb, fo, fi);
            float sum = 0.0f;
#pragma unroll
            for (int i = 0; i < KTOP; i++) sum += fo[i];
            const float s = 1.5f / sum;
            const size_t row = (size_t)(mBase + r);
#pragma unroll
            for (int i = 0; i < KTOP; i++) {
                out[row * KTOP + i] = fo[i] * s;
                out[(size_t)N_ROWS * KTOP + row * KTOP + i] = (float)fi[i];
            }
        }
    }
}

extern "C" void kernel_launch(void* const* d_in, const int* in_sizes, int n_in,
                              void* d_out, int out_size) {
    const float* x      = (const float*)d_in[0];   // [N, D]
    const float* weight = (const float*)d_in[1];   // [E, D]
    const float* bias   = (const float*)d_in[2];   // [E]
    float* out = (float*)d_out;

    preconvert_B<<<(NEXP * DDIM / 4) / 256, 256>>>(weight);
    cudaFuncSetAttribute(gate_main, cudaFuncAttributeMaxDynamicSharedMemorySize, SMEM_TOTAL);
    gate_main<<<N_ROWS / BM, NTHREADS, SMEM_TOTAL>>>(x, bias, out);
}